// round 4
// baseline (speedup 1.0000x reference)
#include <cuda_runtime.h>
#include <stdint.h>
#include <string.h>

#define NIMG 8
#define H 1024
#define W 1024
#define HW (1 << 20)
#define NP 10000
#define PYR_SZ (1 << 21)

// ---------------- scratch (static device globals; no allocation) -------------
__device__ float g_edge[NIMG * HW];            // 32 MB
__device__ float g_theta[NIMG * HW];           // 32 MB
__device__ unsigned char g_mask[NIMG * HW];    // 8 MB
__device__ float g_pyr[NIMG * PYR_SZ];         // 64 MB  (cumsum tree, 21 levels)
__device__ unsigned int g_edgemax[NIMG];
__device__ int g_maskcnt[NIMG];
__device__ unsigned int g_maxdiff[NIMG];
__device__ int g_validcnt[NIMG];
__device__ double g_sum_eq[NIMG];
__device__ double g_sum_ne[NIMG];
__device__ float g_tvals[NIMG][NP][4];
__device__ float g_ivals[NIMG][NP][4];
__device__ unsigned char g_validf[NIMG][NP];

struct LaunchParams {
  uint32_t k1[NIMG][2];   // choice key
  uint32_t k2a[NIMG][2];  // randint higher-bits key
  uint32_t k2b[NIMG][2];  // randint lower-bits key
  uint32_t pdir[NIMG];    // uniform(k3) < 0.5
};

// ---------------- Threefry-2x32 core (exact JAX implementation) --------------
__host__ __device__ __forceinline__ void threefry2x32(uint32_t k0, uint32_t k1,
                                                      uint32_t x0, uint32_t x1,
                                                      uint32_t& o0, uint32_t& o1) {
  uint32_t ks0 = k0, ks1 = k1, ks2 = k0 ^ k1 ^ 0x1BD11BDAu;
  x0 += ks0; x1 += ks1;
#define TF_R(r) { x0 += x1; x1 = (x1 << (r)) | (x1 >> (32 - (r))); x1 ^= x0; }
  TF_R(13) TF_R(15) TF_R(26) TF_R(6)  x0 += ks1; x1 += ks2 + 1u;
  TF_R(17) TF_R(29) TF_R(16) TF_R(24) x0 += ks2; x1 += ks0 + 2u;
  TF_R(13) TF_R(15) TF_R(26) TF_R(6)  x0 += ks0; x1 += ks1 + 3u;
  TF_R(17) TF_R(29) TF_R(16) TF_R(24) x0 += ks1; x1 += ks2 + 4u;
  TF_R(13) TF_R(15) TF_R(26) TF_R(6)  x0 += ks2; x1 += ks0 + 5u;
#undef TF_R
  o0 = x0; o1 = x1;
}

// ---- jax_threefry_partitionable=True (default in modern JAX) conventions ----
// Block at 64-bit counter c (c < 2^32 here): (o0,o1) = threefry(key, hi32(c)=0, lo32(c)=c)
__host__ __device__ __forceinline__ void tf_block(const uint32_t k[2], uint32_t ctr,
                                                  uint32_t& o0, uint32_t& o1) {
  threefry2x32(k[0], k[1], 0u, ctr, o0, o1);
}
// random_bits(key, 32, shape)[i]: partitionable 32-bit extraction = XOR of the
// two output lanes of block i (uses all 64 bits of block entropy).
__host__ __device__ __forceinline__ uint32_t pbits32(const uint32_t k[2], uint32_t ctr) {
  uint32_t o0, o1; tf_block(k, ctr, o0, o1); return o0 ^ o1;
}

__host__ __device__ __forceinline__ int lvlOff(int b) {
  return (1 << 21) - (1 << (21 - b));  // level b (block size 2^b) base offset
}

// ---------------- kernels ----------------------------------------------------
__global__ void k_init() {
  int i = threadIdx.x;
  if (i < NIMG) {
    g_edgemax[i] = 0u; g_maskcnt[i] = 0; g_maxdiff[i] = 0u; g_validcnt[i] = 0;
    g_sum_eq[i] = 0.0; g_sum_ne[i] = 0.0;
  }
}

__global__ void k_sobel(const float* __restrict__ images) {
  int img = blockIdx.y;
  int pix = blockIdx.x * blockDim.x + threadIdx.x;
  int r = pix >> 10, c = pix & (W - 1);
  float e = 0.f, t = 0.f;
  const float* x = images + (size_t)img * 3 * HW;  // channel 0 only
  if (r >= 1 && r <= H - 2 && c >= 1 && c <= W - 2) {
    float a00 = x[(r - 1) * W + c - 1], a01 = x[(r - 1) * W + c], a02 = x[(r - 1) * W + c + 1];
    float a10 = x[r * W + c - 1],                                  a12 = x[r * W + c + 1];
    float a20 = x[(r + 1) * W + c - 1], a21 = x[(r + 1) * W + c], a22 = x[(r + 1) * W + c + 1];
    // accumulate in kernel-window (row-major tap) order; products exact (w=±1,±2)
    float gx = __fmul_rn(-1.f, a00);
    gx = __fadd_rn(gx, a02);
    gx = __fadd_rn(gx, __fmul_rn(-2.f, a10));
    gx = __fadd_rn(gx, __fmul_rn(2.f, a12));
    gx = __fadd_rn(gx, __fmul_rn(-1.f, a20));
    gx = __fadd_rn(gx, a22);
    float gy = a00;
    gy = __fadd_rn(gy, __fmul_rn(2.f, a01));
    gy = __fadd_rn(gy, a02);
    gy = __fadd_rn(gy, __fmul_rn(-1.f, a20));
    gy = __fadd_rn(gy, __fmul_rn(-2.f, a21));
    gy = __fadd_rn(gy, __fmul_rn(-1.f, a22));
    float s = __fadd_rn(__fmul_rn(gx, gx), __fmul_rn(gy, gy));
    e = sqrtf(s);
    t = atan2f(gy, gx);
  }
  g_edge[(size_t)img * HW + pix] = e;
  g_theta[(size_t)img * HW + pix] = t;
  unsigned um = __reduce_max_sync(0xFFFFFFFFu, __float_as_uint(e));  // e >= 0
  if ((threadIdx.x & 31) == 0) atomicMax(&g_edgemax[img], um);
}

__global__ void k_mask(const float* __restrict__ tgt, const float* __restrict__ depth) {
  int img = blockIdx.y;
  int pix = blockIdx.x * blockDim.x + threadIdx.x;
  float thresh = __fmul_rn(0.1f, __uint_as_float(g_edgemax[img]));
  float e = g_edge[(size_t)img * HW + pix];
  float d = depth[(size_t)img * HW + pix];
  float tg = tgt[(size_t)img * HW + pix];
  bool strict = (d > -0.001f) && (d < 80.0f) && !(tg == 80.0f);
  bool m = (e >= thresh) && strict;
  g_mask[(size_t)img * HW + pix] = m ? 1 : 0;
  unsigned bal = __ballot_sync(0xFFFFFFFFu, m);
  if ((threadIdx.x & 31) == 0) atomicAdd(&g_maskcnt[img], __popc(bal));
}

__global__ void k_leaf() {
  int img = blockIdx.y;
  int pix = blockIdx.x * blockDim.x + threadIdx.x;
  float S = (float)g_maskcnt[img];                 // exact (0/1 sum < 2^24)
  float v = __fdiv_rn(1.0f, fmaxf(S, 1.0f));      // p = 1/max(S,1), IEEE rn
  g_pyr[(size_t)img * PYR_SZ + pix] = g_mask[(size_t)img * HW + pix] ? v : 0.0f;
}

__global__ void k_level(int srcOff, int dstOff, int n) {
  int img = blockIdx.y;
  int i = blockIdx.x * blockDim.x + threadIdx.x;
  if (i >= n) return;
  float* base = g_pyr + (size_t)img * PYR_SZ;
  base[dstOff + i] = __fadd_rn(base[srcOff + 2 * i], base[srcOff + 2 * i + 1]);
}

// Levels b=8..20 fused: one block per image, barrier between levels.
// Bit-identical pairwise __fadd_rn tree, 13 launches -> 1.
__global__ void k_level_tail() {
  int img = blockIdx.x;
  float* base = g_pyr + (size_t)img * PYR_SZ;
  for (int b = 8; b <= 20; b++) {
    int n = 1 << (20 - b);
    int srcOff = lvlOff(b - 1), dstOff = lvlOff(b);
    for (int i = threadIdx.x; i < n; i += blockDim.x)
      base[dstOff + i] = __fadd_rn(base[srcOff + 2 * i], base[srcOff + 2 * i + 1]);
    __syncthreads();
  }
}

__global__ void k_sample(LaunchParams P, const float* __restrict__ inp,
                         const float* __restrict__ tgt) {
  int j = blockIdx.x * blockDim.x + threadIdx.x;
  int img = blockIdx.y;
  if (j >= NP) return;
  const float* pyr = g_pyr + (size_t)img * PYR_SZ;

  // uniform(k1, (NP,))[j]  (partitionable: xor-fold of block j lanes)
  uint32_t ub = pbits32(P.k1[img], (uint32_t)j);
  float u = __uint_as_float((ub >> 9) | 0x3F800000u) - 1.0f;
  float T = __ldg(&pyr[lvlOff(20)]);               // p_cuml[-1] (tree total)
  float r = __fmul_rn(T, __fsub_rn(1.0f, u));

  // jnp.searchsorted 'scan' replica: 21 iters, go_left = (query <= a[mid])
  int low = 0, high = 1 << 20;
#pragma unroll 1
  for (int it = 0; it < 21; it++) {
    int mid = (low + high) >> 1;
    uint32_t m = (uint32_t)mid + 1u;
    float acc = 0.0f;
    uint32_t off = 0;
#pragma unroll
    for (int b = 20; b >= 0; b--) {                // associative_scan association
      if ((m >> b) & 1u) {
        acc = __fadd_rn(acc, __ldg(&pyr[lvlOff(b) + (off >> b)]));
        off += (1u << b);
      }
    }
    if (r <= acc) high = mid; else low = mid;
  }
  int idx = high; if (idx > HW - 1) idx = HW - 1;

  int sh = idx >> 10, sw = idx & (W - 1);
  float th = __ldg(&g_theta[(size_t)img * HW + idx]);
  float c0 = cosf(th), s0 = sinf(th);
  // th2 = mod(th + pi/2 + pi, 2pi) - pi  (jnp.mod sign fix; x>0 here anyway)
  float xx = __fadd_rn(__fadd_rn(th, 1.5707964f), 3.1415927f);
  float tm = fmodf(xx, 6.2831855f);
  if (tm != 0.0f && tm < 0.0f) tm = __fadd_rn(tm, 6.2831855f);
  float th2 = __fsub_rn(tm, 3.1415927f);
  float s2 = sinf(th2), c2 = cosf(th2);
  bool pd = P.pdir[img] != 0;

  int rows[4], cols[4];
  bool ok = true;
#pragma unroll
  for (int i = 0; i < 4; i++) {
    // randint(k2,(4,NP),2,31): span=29, multiplier=(2^16%29)^2%29=16
    uint32_t f = (uint32_t)(i * NP + j);
    uint32_t hb = pbits32(P.k2a[img], f);
    uint32_t lb = pbits32(P.k2b[img], f);
    uint32_t offr = ((hb % 29u) * 16u + (lb % 29u)) % 29u;
    float d = (float)(2u + offr);
    if (i < 2) d = -d;                              // sign = [-1,-1,1,1]
    int col, row;
    if (pd) {
      col = sw + (int)rintf(__fmul_rn(d, c0));      // round half-to-even
      row = sh + (int)rintf(__fmul_rn(d, s0));
    } else {
      col = sw + (int)rintf(__fmul_rn(d, s2));
      row = sh + (int)rintf(__fmul_rn(d, c2));
    }
    ok = ok && (col >= 0) && (col <= W - 1) && (row >= 0) && (row <= H - 1);
    cols[i] = min(max(col, 0), W - 1);
    rows[i] = min(max(row, 0), H - 1);
  }
  const float* ip = inp + (size_t)img * HW;
  const float* tp = tgt + (size_t)img * HW;
  float tv[4];
#pragma unroll
  for (int i = 0; i < 4; i++) {
    int p = rows[i] * W + cols[i];
    float ivv = __ldg(&ip[p]);
    tv[i] = __ldg(&tp[p]);
    g_ivals[img][j][i] = ivv;
    g_tvals[img][j][i] = tv[i];
  }
  g_validf[img][j] = ok ? 1 : 0;
  if (ok) {
    float m0 = fabsf(__fsub_rn(tv[0], tv[1]));
    float m1 = fabsf(__fsub_rn(tv[1], tv[2]));
    float m2 = fabsf(__fsub_rn(tv[2], tv[3]));
    float mm = fmaxf(m0, fmaxf(m1, m2));
    atomicMax(&g_maxdiff[img], __float_as_uint(mm));
    atomicAdd(&g_validcnt[img], 1);
  }
}

__global__ void k_loss() {
  int j = blockIdx.x * blockDim.x + threadIdx.x;
  int img = blockIdx.y;
  double se = 0.0, sn = 0.0;
  if (j < NP) {
    float md = __uint_as_float(g_maxdiff[img]);
    float denom = __fadd_rn(md, 1e-6f);
    float vm = g_validf[img][j] ? 1.0f : 0.0f;
    const float CHI = (float)(1.0 + 0.03);
    const float CLO = (float)(1.0 / (1.0 + 0.03));
#pragma unroll
    for (int k = 0; k < 3; k++) {
      float tA = g_tvals[img][j][k], tB = g_tvals[img][j][k + 1];
      float iA = g_ivals[img][j][k], iB = g_ivals[img][j][k + 1];
      float ratio = __fdiv_rn(__fadd_rn(tA, 1e-6f), __fadd_rn(tB, 1e-6f));
      float ad = fabsf(__fsub_rn(tA, tB));
      float tw = expf(__fdiv_rn(ad, denom));
      bool eqb = (ratio < CHI) && (ratio > CLO);
      float eqf = eqb ? 1.0f : 0.0f;
      float label = (ratio >= CHI) ? 1.0f : ((ratio <= CLO) ? -1.0f : 0.0f);
      float dd = __fsub_rn(iA, iB);
      float el = __fmul_rn(__fdiv_rn(__fmul_rn(dd, dd), tw), eqf);
      float z = __fmul_rn(__fsub_rn(iB, iA), label);
      float ue = __fmul_rn(log1pf(expf(z)), __fsub_rn(1.0f, eqf));
      se += (double)__fmul_rn(el, vm);
      sn += (double)__fmul_rn(ue, vm);
    }
  }
  __shared__ double sh_se[128];
  __shared__ double sh_sn[128];
  sh_se[threadIdx.x] = se; sh_sn[threadIdx.x] = sn;
  __syncthreads();
  for (int s = blockDim.x / 2; s > 0; s >>= 1) {
    if ((int)threadIdx.x < s) {
      sh_se[threadIdx.x] += sh_se[threadIdx.x + s];
      sh_sn[threadIdx.x] += sh_sn[threadIdx.x + s];
    }
    __syncthreads();
  }
  if (threadIdx.x == 0) {
    atomicAdd(&g_sum_eq[img], sh_se[0]);
    atomicAdd(&g_sum_ne[img], sh_sn[0]);
  }
}

__global__ void k_final(float* out, int out_size) {
  if (threadIdx.x == 0 && blockIdx.x == 0) {
    float ls = 0.f, cs = 0.f;
    for (int i = 0; i < NIMG; i++) {
      float nv = 3.0f * (float)g_validcnt[i];
      float cnt = fmaxf(nv, 1.0f);
      float li = (float)(g_sum_eq[i] / (double)cnt + g_sum_ne[i] / (double)cnt);
      ls += li; cs += nv;
    }
    if (out_size >= 1) out[0] = ls / 8.0f;
    if (out_size >= 2) out[1] = cs / 8.0f;
  }
}

// ---------------- host --------------------------------------------------------
extern "C" void kernel_launch(void* const* d_in, const int* in_sizes, int n_in,
                              void* d_out, int out_size) {
  const float* inputs  = (const float*)d_in[0];
  const float* targets = (const float*)d_in[1];
  const float* images  = (const float*)d_in[2];
  const float* depth   = (const float*)d_in[3];
  float* out = (float*)d_out;
  (void)in_sizes; (void)n_in;

  // Host-side key derivation, jax_threefry_partitionable=True conventions:
  //   split(key, n): child i = raw lanes (o0, o1) of threefry(key, 0, i)
  //   random_bits(key, 32)[i] = o0 ^ o1 of block i
  LaunchParams P;
  uint32_t root[2] = {0u, 42u};   // jax.random.key(42)
  for (int i = 0; i < NIMG; i++) {
    uint32_t ik[2];
    tf_block(root, (uint32_t)i, ik[0], ik[1]);         // keys = split(key(42), 8)
    uint32_t k1[2], k2[2], k3[2];
    tf_block(ik, 0u, k1[0], k1[1]);                    // k1,k2,k3 = split(key, 3)
    tf_block(ik, 1u, k2[0], k2[1]);
    tf_block(ik, 2u, k3[0], k3[1]);
    P.k1[i][0] = k1[0]; P.k1[i][1] = k1[1];
    tf_block(k2, 0u, P.k2a[i][0], P.k2a[i][1]);        // randint: ka, kb = split(k2)
    tf_block(k2, 1u, P.k2b[i][0], P.k2b[i][1]);
    uint32_t bits = pbits32(k3, 0u);                   // uniform(k3) scalar
    uint32_t fb = (bits >> 9) | 0x3F800000u;
    float uu; memcpy(&uu, &fb, 4); uu -= 1.0f;
    P.pdir[i] = (uu < 0.5f) ? 1u : 0u;
  }

  k_init<<<1, 32>>>();
  dim3 bs(256), gs(HW / 256, NIMG);
  k_sobel<<<gs, bs>>>(images);
  k_mask<<<gs, bs>>>(targets, depth);
  k_leaf<<<gs, bs>>>();
  for (int b = 1; b <= 7; b++) {
    int n = 1 << (20 - b);
    dim3 g2((n + 255) / 256, NIMG);
    k_level<<<g2, 256>>>(lvlOff(b - 1), lvlOff(b), n);
  }
  k_level_tail<<<NIMG, 1024>>>();
  dim3 gsamp((NP + 127) / 128, NIMG);
  k_sample<<<gsamp, 128>>>(P, inputs, targets);
  k_loss<<<gsamp, 128>>>();
  k_final<<<1, 1>>>(out, out_size);
}

// round 6
// speedup vs baseline: 3.0289x; 3.0289x over previous
#include <cuda_runtime.h>
#include <stdint.h>
#include <string.h>

#define NIMG 8
#define H 1024
#define W 1024
#define HW (1 << 20)
#define NWORDS (HW / 32)
#define NP 10000
#define PYR_SZ (1 << 21)

// ---------------- scratch (static device globals; no allocation) -------------
__device__ float g_pyr[NIMG * PYR_SZ];            // 64 MB (levels 1..20 used)
__device__ uint32_t g_maskbits[NIMG * NWORDS];    // 1 MB bit-packed mask
__device__ unsigned int g_edgemax[NIMG];
__device__ int g_maskcnt[NIMG];
__device__ unsigned int g_maxdiff[NIMG];
__device__ int g_validcnt[NIMG];
__device__ double g_sum_eq[NIMG];
__device__ double g_sum_ne[NIMG];
__device__ float g_tvals[NIMG][NP][4];
__device__ float g_ivals[NIMG][NP][4];
__device__ unsigned char g_validf[NIMG][NP];

struct LaunchParams {
  uint32_t k1[NIMG][2];   // choice key
  uint32_t k2a[NIMG][2];  // randint higher-bits key
  uint32_t k2b[NIMG][2];  // randint lower-bits key
  uint32_t pdir[NIMG];    // uniform(k3) < 0.5
};

// ---------------- Threefry-2x32 core (exact JAX implementation) --------------
__host__ __device__ __forceinline__ void threefry2x32(uint32_t k0, uint32_t k1,
                                                      uint32_t x0, uint32_t x1,
                                                      uint32_t& o0, uint32_t& o1) {
  uint32_t ks0 = k0, ks1 = k1, ks2 = k0 ^ k1 ^ 0x1BD11BDAu;
  x0 += ks0; x1 += ks1;
#define TF_R(r) { x0 += x1; x1 = (x1 << (r)) | (x1 >> (32 - (r))); x1 ^= x0; }
  TF_R(13) TF_R(15) TF_R(26) TF_R(6)  x0 += ks1; x1 += ks2 + 1u;
  TF_R(17) TF_R(29) TF_R(16) TF_R(24) x0 += ks2; x1 += ks0 + 2u;
  TF_R(13) TF_R(15) TF_R(26) TF_R(6)  x0 += ks0; x1 += ks1 + 3u;
  TF_R(17) TF_R(29) TF_R(16) TF_R(24) x0 += ks1; x1 += ks2 + 4u;
  TF_R(13) TF_R(15) TF_R(26) TF_R(6)  x0 += ks2; x1 += ks0 + 5u;
#undef TF_R
  o0 = x0; o1 = x1;
}

// jax_threefry_partitionable=True conventions (confirmed by round-4 PASS):
// split child / block at counter c: threefry(key, 0, c); 32-bit draw = o0 ^ o1.
__host__ __device__ __forceinline__ void tf_block(const uint32_t k[2], uint32_t ctr,
                                                  uint32_t& o0, uint32_t& o1) {
  threefry2x32(k[0], k[1], 0u, ctr, o0, o1);
}
__host__ __device__ __forceinline__ uint32_t pbits32(const uint32_t k[2], uint32_t ctr) {
  uint32_t o0, o1; tf_block(k, ctr, o0, o1); return o0 ^ o1;
}

__host__ __device__ __forceinline__ int lvlOff(int b) {
  return (1 << 21) - (1 << (21 - b));  // level b (block size 2^b) base offset
}

// Sobel gx/gy for interior pixel, bit-identical tap order. Returns false at border.
__device__ __forceinline__ bool sobel_gxgy(const float* __restrict__ x, int pix,
                                           float& gx, float& gy) {
  int r = pix >> 10, c = pix & (W - 1);
  if (r < 1 || r > H - 2 || c < 1 || c > W - 2) return false;
  float a00 = x[(r - 1) * W + c - 1], a01 = x[(r - 1) * W + c], a02 = x[(r - 1) * W + c + 1];
  float a10 = x[r * W + c - 1],                                  a12 = x[r * W + c + 1];
  float a20 = x[(r + 1) * W + c - 1], a21 = x[(r + 1) * W + c], a22 = x[(r + 1) * W + c + 1];
  gx = __fmul_rn(-1.f, a00);
  gx = __fadd_rn(gx, a02);
  gx = __fadd_rn(gx, __fmul_rn(-2.f, a10));
  gx = __fadd_rn(gx, __fmul_rn(2.f, a12));
  gx = __fadd_rn(gx, __fmul_rn(-1.f, a20));
  gx = __fadd_rn(gx, a22);
  gy = a00;
  gy = __fadd_rn(gy, __fmul_rn(2.f, a01));
  gy = __fadd_rn(gy, a02);
  gy = __fadd_rn(gy, __fmul_rn(-1.f, a20));
  gy = __fadd_rn(gy, __fmul_rn(-2.f, a21));
  gy = __fadd_rn(gy, __fmul_rn(-1.f, a22));
  return true;
}
__device__ __forceinline__ float sobel_edge(const float* __restrict__ x, int pix) {
  float gx, gy;
  if (!sobel_gxgy(x, pix, gx, gy)) return 0.f;
  return sqrtf(__fadd_rn(__fmul_rn(gx, gx), __fmul_rn(gy, gy)));
}

// ---------------- kernels ----------------------------------------------------
__global__ void k_init() {
  int i = threadIdx.x;
  if (i < NIMG) {
    g_edgemax[i] = 0u; g_maskcnt[i] = 0; g_maxdiff[i] = 0u; g_validcnt[i] = 0;
    g_sum_eq[i] = 0.0; g_sum_ne[i] = 0.0;
  }
}

__global__ void k_edgemax(const float* __restrict__ images) {
  int img = blockIdx.y;
  int pix = blockIdx.x * blockDim.x + threadIdx.x;
  const float* x = images + (size_t)img * 3 * HW;   // channel 0
  float e = sobel_edge(x, pix);
  unsigned um = __reduce_max_sync(0xFFFFFFFFu, __float_as_uint(e));  // e >= 0
  __shared__ unsigned sm[8];
  if ((threadIdx.x & 31) == 0) sm[threadIdx.x >> 5] = um;
  __syncthreads();
  if (threadIdx.x == 0) {
    unsigned mx = sm[0];
#pragma unroll
    for (int w = 1; w < 8; w++) mx = max(mx, sm[w]);
    atomicMax(&g_edgemax[img], mx);
  }
}

__global__ void k_mask(const float* __restrict__ images, const float* __restrict__ tgt,
                       const float* __restrict__ depth) {
  int img = blockIdx.y;
  int pix = blockIdx.x * blockDim.x + threadIdx.x;
  float thresh = __fmul_rn(0.1f, __uint_as_float(g_edgemax[img]));
  const float* x = images + (size_t)img * 3 * HW;
  float e = sobel_edge(x, pix);
  float d = depth[(size_t)img * HW + pix];
  float tg = tgt[(size_t)img * HW + pix];
  bool m = (e >= thresh) && (d > -0.001f) && (d < 80.0f) && !(tg == 80.0f);
  unsigned bal = __ballot_sync(0xFFFFFFFFu, m);
  int warp = threadIdx.x >> 5;
  if ((threadIdx.x & 31) == 0)
    g_maskbits[img * NWORDS + (blockIdx.x * (blockDim.x >> 5)) + warp] = bal;
  __shared__ int cnts[8];
  if ((threadIdx.x & 31) == 0) cnts[warp] = __popc(bal);
  __syncthreads();
  if (threadIdx.x == 0) {
    int s = 0;
#pragma unroll
    for (int w = 0; w < 8; w++) s += cnts[w];
    atomicAdd(&g_maskcnt[img], s);
  }
}

// Level 1 from bit-packed mask: each thread consumes one 32-bit word -> 16 outputs.
__global__ void k_lvl1() {
  int img = blockIdx.y;
  int wi = blockIdx.x * blockDim.x + threadIdx.x;           // word index 0..NWORDS-1
  float S = (float)g_maskcnt[img];                          // exact
  float v = __fdiv_rn(1.0f, fmaxf(S, 1.0f));
  uint32_t wrd = g_maskbits[img * NWORDS + wi];
  float o[16];
#pragma unroll
  for (int k = 0; k < 16; k++) {
    float l0 = ((wrd >> (2 * k)) & 1u) ? v : 0.f;
    float l1 = ((wrd >> (2 * k + 1)) & 1u) ? v : 0.f;
    o[k] = __fadd_rn(l0, l1);
  }
  float4* d4 = (float4*)(g_pyr + (size_t)img * PYR_SZ + lvlOff(1) + wi * 16);
#pragma unroll
  for (int k = 0; k < 4; k++)
    d4[k] = make_float4(o[4 * k], o[4 * k + 1], o[4 * k + 2], o[4 * k + 3]);
}

// Generic vectorized level: 4 outputs per thread.
__global__ void k_lvl4x(int srcOff, int dstOff, int nOut) {
  int img = blockIdx.y;
  int i = blockIdx.x * blockDim.x + threadIdx.x;
  if (i * 4 >= nOut) return;
  const float4* src = (const float4*)(g_pyr + (size_t)img * PYR_SZ + srcOff);
  float4 a = src[2 * i], b = src[2 * i + 1];
  float4 o;
  o.x = __fadd_rn(a.x, a.y); o.y = __fadd_rn(a.z, a.w);
  o.z = __fadd_rn(b.x, b.y); o.w = __fadd_rn(b.z, b.w);
  ((float4*)(g_pyr + (size_t)img * PYR_SZ + dstOff))[i] = o;
}

// Levels b=5..20 fused: one block per image, barrier between levels.
__global__ void k_level_tail() {
  int img = blockIdx.x;
  float* base = g_pyr + (size_t)img * PYR_SZ;
  for (int b = 5; b <= 20; b++) {
    int n = 1 << (20 - b);
    int srcOff = lvlOff(b - 1), dstOff = lvlOff(b);
    for (int i = threadIdx.x; i < n; i += blockDim.x)
      base[dstOff + i] = __fadd_rn(base[srcOff + 2 * i], base[srcOff + 2 * i + 1]);
    __syncthreads();
  }
}

__device__ __forceinline__ float leaf_at(const uint32_t* __restrict__ mb, int i, float v) {
  uint32_t wrd = __ldg(&mb[i >> 5]);
  return ((wrd >> (i & 31)) & 1u) ? v : 0.f;
}

// Generic cumsum[m-1] evaluation via aligned-block decomposition of m
// (reference associative_scan association, descending-bit fadd order).
__device__ __forceinline__ float cumsum_generic(const float* __restrict__ pyr,
                                                const uint32_t* __restrict__ mb,
                                                float v, uint32_t m) {
  float acc = 0.f;
  uint32_t off = 0;
#pragma unroll
  for (int b = 20; b >= 1; b--) {
    if ((m >> b) & 1u) {
      acc = __fadd_rn(acc, __ldg(&pyr[lvlOff(b) + (off >> b)]));
      off += (1u << b);
    }
  }
  if (m & 1u) acc = __fadd_rn(acc, leaf_at(mb, (int)off, v));
  return acc;
}

__global__ void k_sample(LaunchParams P, const float* __restrict__ inp,
                         const float* __restrict__ tgt,
                         const float* __restrict__ images) {
  int j = blockIdx.x * blockDim.x + threadIdx.x;
  int img = blockIdx.y;
  if (j >= NP) return;
  const float* pyr = g_pyr + (size_t)img * PYR_SZ;
  const uint32_t* mb = g_maskbits + img * NWORDS;
  float S = (float)g_maskcnt[img];
  float v = __fdiv_rn(1.0f, fmaxf(S, 1.0f));

  // uniform(k1, (NP,))[j]
  uint32_t ub = pbits32(P.k1[img], (uint32_t)j);
  float u = __uint_as_float((ub >> 9) | 0x3F800000u) - 1.0f;
  float T = __ldg(&pyr[lvlOff(20)]);               // p_cuml[-1]
  float r = __fmul_rn(T, __fsub_rn(1.0f, u));

  // searchsorted 'scan': iterations 0..18 via exact incremental tree descent.
  // cumsum[mid] for m=mid+1 = low + 2^b + 1 (no carries): A(low) (+) node_b (+) leaf(mid),
  // fadd chain in the reference's descending-bit order.
  int low = 0;
  float A = 0.f;
#pragma unroll 1
  for (int b = 19; b >= 1; b--) {
    int mid = low + (1 << b);
    float t1 = __fadd_rn(A, __ldg(&pyr[lvlOff(b) + (low >> b)]));
    float acc = __fadd_rn(t1, leaf_at(mb, mid, v));
    if (!(r <= acc)) { A = t1; low = mid; }
  }
  // it=19 (m=low+2, may carry) and it=20 (m=low+1, may carry): generic eval.
  {
    float acc = cumsum_generic(pyr, mb, v, (uint32_t)low + 2u);
    if (!(r <= acc)) low = low + 1;
  }
  int idx;
  {
    float acc = cumsum_generic(pyr, mb, v, (uint32_t)low + 1u);
    idx = (r <= acc) ? low : low + 1;
  }
  if (idx > HW - 1) idx = HW - 1;

  int sh = idx >> 10, sw = idx & (W - 1);
  // theta recomputed at idx (bit-identical to reference sobel + atan2f; 0 at border)
  float th = 0.f;
  {
    float gx, gy;
    const float* x = images + (size_t)img * 3 * HW;
    if (sobel_gxgy(x, idx, gx, gy)) th = atan2f(gy, gx);
  }
  float c0 = cosf(th), s0 = sinf(th);
  // th2 = mod(th + pi/2 + pi, 2pi) - pi
  float xx = __fadd_rn(__fadd_rn(th, 1.5707964f), 3.1415927f);
  float tm = fmodf(xx, 6.2831855f);
  if (tm != 0.0f && tm < 0.0f) tm = __fadd_rn(tm, 6.2831855f);
  float th2 = __fsub_rn(tm, 3.1415927f);
  float s2 = sinf(th2), c2 = cosf(th2);
  bool pd = P.pdir[img] != 0;

  int rows[4], cols[4];
  bool ok = true;
#pragma unroll
  for (int i = 0; i < 4; i++) {
    // randint(k2,(4,NP),2,31): span=29, multiplier=(2^16%29)^2%29=16
    uint32_t f = (uint32_t)(i * NP + j);
    uint32_t hb = pbits32(P.k2a[img], f);
    uint32_t lb = pbits32(P.k2b[img], f);
    uint32_t offr = ((hb % 29u) * 16u + (lb % 29u)) % 29u;
    float d = (float)(2u + offr);
    if (i < 2) d = -d;                              // sign = [-1,-1,1,1]
    int col, row;
    if (pd) {
      col = sw + (int)rintf(__fmul_rn(d, c0));
      row = sh + (int)rintf(__fmul_rn(d, s0));
    } else {
      col = sw + (int)rintf(__fmul_rn(d, s2));
      row = sh + (int)rintf(__fmul_rn(d, c2));
    }
    ok = ok && (col >= 0) && (col <= W - 1) && (row >= 0) && (row <= H - 1);
    cols[i] = min(max(col, 0), W - 1);
    rows[i] = min(max(row, 0), H - 1);
  }
  const float* ip = inp + (size_t)img * HW;
  const float* tp = tgt + (size_t)img * HW;
  float tv[4];
#pragma unroll
  for (int i = 0; i < 4; i++) {
    int p = rows[i] * W + cols[i];
    float ivv = __ldg(&ip[p]);
    tv[i] = __ldg(&tp[p]);
    g_ivals[img][j][i] = ivv;
    g_tvals[img][j][i] = tv[i];
  }
  g_validf[img][j] = ok ? 1 : 0;
  if (ok) {
    float m0 = fabsf(__fsub_rn(tv[0], tv[1]));
    float m1 = fabsf(__fsub_rn(tv[1], tv[2]));
    float m2 = fabsf(__fsub_rn(tv[2], tv[3]));
    float mm = fmaxf(m0, fmaxf(m1, m2));
    atomicMax(&g_maxdiff[img], __float_as_uint(mm));
    atomicAdd(&g_validcnt[img], 1);
  }
}

__global__ void k_loss() {
  int j = blockIdx.x * blockDim.x + threadIdx.x;
  int img = blockIdx.y;
  double se = 0.0, sn = 0.0;
  if (j < NP) {
    float md = __uint_as_float(g_maxdiff[img]);
    float denom = __fadd_rn(md, 1e-6f);
    float vm = g_validf[img][j] ? 1.0f : 0.0f;
    const float CHI = (float)(1.0 + 0.03);
    const float CLO = (float)(1.0 / (1.0 + 0.03));
#pragma unroll
    for (int k = 0; k < 3; k++) {
      float tA = g_tvals[img][j][k], tB = g_tvals[img][j][k + 1];
      float iA = g_ivals[img][j][k], iB = g_ivals[img][j][k + 1];
      float ratio = __fdiv_rn(__fadd_rn(tA, 1e-6f), __fadd_rn(tB, 1e-6f));
      float ad = fabsf(__fsub_rn(tA, tB));
      float tw = expf(__fdiv_rn(ad, denom));
      bool eqb = (ratio < CHI) && (ratio > CLO);
      float eqf = eqb ? 1.0f : 0.0f;
      float label = (ratio >= CHI) ? 1.0f : ((ratio <= CLO) ? -1.0f : 0.0f);
      float dd = __fsub_rn(iA, iB);
      float el = __fmul_rn(__fdiv_rn(__fmul_rn(dd, dd), tw), eqf);
      float z = __fmul_rn(__fsub_rn(iB, iA), label);
      float ue = __fmul_rn(log1pf(expf(z)), __fsub_rn(1.0f, eqf));
      se += (double)__fmul_rn(el, vm);
      sn += (double)__fmul_rn(ue, vm);
    }
  }
  __shared__ double sh_se[128];
  __shared__ double sh_sn[128];
  sh_se[threadIdx.x] = se; sh_sn[threadIdx.x] = sn;
  __syncthreads();
  for (int s = blockDim.x / 2; s > 0; s >>= 1) {
    if ((int)threadIdx.x < s) {
      sh_se[threadIdx.x] += sh_se[threadIdx.x + s];
      sh_sn[threadIdx.x] += sh_sn[threadIdx.x + s];
    }
    __syncthreads();
  }
  if (threadIdx.x == 0) {
    atomicAdd(&g_sum_eq[img], sh_se[0]);
    atomicAdd(&g_sum_ne[img], sh_sn[0]);
  }
}

__global__ void k_final(float* out, int out_size) {
  if (threadIdx.x == 0 && blockIdx.x == 0) {
    float ls = 0.f, cs = 0.f;
    for (int i = 0; i < NIMG; i++) {
      float nv = 3.0f * (float)g_validcnt[i];
      float cnt = fmaxf(nv, 1.0f);
      float li = (float)(g_sum_eq[i] / (double)cnt + g_sum_ne[i] / (double)cnt);
      ls += li; cs += nv;
    }
    if (out_size >= 1) out[0] = ls / 8.0f;
    if (out_size >= 2) out[1] = cs / 8.0f;
  }
}

// ---------------- host --------------------------------------------------------
extern "C" void kernel_launch(void* const* d_in, const int* in_sizes, int n_in,
                              void* d_out, int out_size) {
  const float* inputs  = (const float*)d_in[0];
  const float* targets = (const float*)d_in[1];
  const float* images  = (const float*)d_in[2];
  const float* depth   = (const float*)d_in[3];
  float* out = (float*)d_out;
  (void)in_sizes; (void)n_in;

  LaunchParams P;
  uint32_t root[2] = {0u, 42u};   // jax.random.key(42)
  for (int i = 0; i < NIMG; i++) {
    uint32_t ik[2];
    tf_block(root, (uint32_t)i, ik[0], ik[1]);         // keys = split(key(42), 8)
    uint32_t k1[2], k2[2], k3[2];
    tf_block(ik, 0u, k1[0], k1[1]);                    // k1,k2,k3 = split(key, 3)
    tf_block(ik, 1u, k2[0], k2[1]);
    tf_block(ik, 2u, k3[0], k3[1]);
    P.k1[i][0] = k1[0]; P.k1[i][1] = k1[1];
    tf_block(k2, 0u, P.k2a[i][0], P.k2a[i][1]);        // randint: ka, kb = split(k2)
    tf_block(k2, 1u, P.k2b[i][0], P.k2b[i][1]);
    uint32_t bits = pbits32(k3, 0u);                   // uniform(k3) scalar
    uint32_t fb = (bits >> 9) | 0x3F800000u;
    float uu; memcpy(&uu, &fb, 4); uu -= 1.0f;
    P.pdir[i] = (uu < 0.5f) ? 1u : 0u;
  }

  k_init<<<1, 32>>>();
  dim3 bs(256), gs(HW / 256, NIMG);
  k_edgemax<<<gs, bs>>>(images);
  k_mask<<<gs, bs>>>(images, targets, depth);
  k_lvl1<<<dim3(NWORDS / 256, NIMG), 256>>>();
  // levels 2..4, 4 outputs/thread
  k_lvl4x<<<dim3((1 << 18) / 4 / 256, NIMG), 256>>>(lvlOff(1), lvlOff(2), 1 << 18);
  k_lvl4x<<<dim3((1 << 17) / 4 / 256, NIMG), 256>>>(lvlOff(2), lvlOff(3), 1 << 17);
  k_lvl4x<<<dim3((1 << 16) / 4 / 256, NIMG), 256>>>(lvlOff(3), lvlOff(4), 1 << 16);
  k_level_tail<<<NIMG, 1024>>>();
  dim3 gsamp((NP + 127) / 128, NIMG);
  k_sample<<<gsamp, 128>>>(P, inputs, targets, images);
  k_loss<<<gsamp, 128>>>();
  k_final<<<1, 1>>>(out, out_size);
}

// round 7
// speedup vs baseline: 4.2885x; 1.4159x over previous
#include <cuda_runtime.h>
#include <stdint.h>
#include <string.h>

#define NIMG 8
#define H 1024
#define W 1024
#define HW (1 << 20)
#define NWORDS (HW / 32)
#define NP 10000
#define PYR_SZ (1 << 21)

// ---------------- scratch (static device globals; no allocation) -------------
__device__ float g_pyr[NIMG * PYR_SZ];            // 64 MB (levels 1..20 used)
__device__ uint32_t g_maskbits[NIMG * NWORDS];    // 1 MB bit-packed mask
__device__ unsigned int g_edgemax[NIMG];
__device__ int g_maskcnt[NIMG];
__device__ unsigned int g_maxdiff[NIMG];
__device__ int g_validcnt[NIMG];
__device__ double g_sum_eq[NIMG];
__device__ double g_sum_ne[NIMG];
__device__ float g_tvals[NIMG][NP][4];
__device__ float g_ivals[NIMG][NP][4];
__device__ unsigned char g_validf[NIMG][NP];

struct LaunchParams {
  uint32_t k1[NIMG][2];   // choice key
  uint32_t k2a[NIMG][2];  // randint higher-bits key
  uint32_t k2b[NIMG][2];  // randint lower-bits key
  uint32_t pdir[NIMG];    // uniform(k3) < 0.5
};

// ---------------- Threefry-2x32 core (exact JAX implementation) --------------
__host__ __device__ __forceinline__ void threefry2x32(uint32_t k0, uint32_t k1,
                                                      uint32_t x0, uint32_t x1,
                                                      uint32_t& o0, uint32_t& o1) {
  uint32_t ks0 = k0, ks1 = k1, ks2 = k0 ^ k1 ^ 0x1BD11BDAu;
  x0 += ks0; x1 += ks1;
#define TF_R(r) { x0 += x1; x1 = (x1 << (r)) | (x1 >> (32 - (r))); x1 ^= x0; }
  TF_R(13) TF_R(15) TF_R(26) TF_R(6)  x0 += ks1; x1 += ks2 + 1u;
  TF_R(17) TF_R(29) TF_R(16) TF_R(24) x0 += ks2; x1 += ks0 + 2u;
  TF_R(13) TF_R(15) TF_R(26) TF_R(6)  x0 += ks0; x1 += ks1 + 3u;
  TF_R(17) TF_R(29) TF_R(16) TF_R(24) x0 += ks1; x1 += ks2 + 4u;
  TF_R(13) TF_R(15) TF_R(26) TF_R(6)  x0 += ks2; x1 += ks0 + 5u;
#undef TF_R
  o0 = x0; o1 = x1;
}

// jax_threefry_partitionable=True conventions (confirmed by round-4 PASS):
__host__ __device__ __forceinline__ void tf_block(const uint32_t k[2], uint32_t ctr,
                                                  uint32_t& o0, uint32_t& o1) {
  threefry2x32(k[0], k[1], 0u, ctr, o0, o1);
}
__host__ __device__ __forceinline__ uint32_t pbits32(const uint32_t k[2], uint32_t ctr) {
  uint32_t o0, o1; tf_block(k, ctr, o0, o1); return o0 ^ o1;
}

__host__ __device__ __forceinline__ int lvlOff(int b) {
  return (1 << 21) - (1 << (21 - b));  // level b (block size 2^b) base offset
}

// ---------------- sobel (bit-identical tap order) -----------------------------
__device__ __forceinline__ void sobel_core(float a00, float a01, float a02,
                                           float a10, float a12,
                                           float a20, float a21, float a22,
                                           float& gx, float& gy) {
  gx = __fmul_rn(-1.f, a00);
  gx = __fadd_rn(gx, a02);
  gx = __fadd_rn(gx, __fmul_rn(-2.f, a10));
  gx = __fadd_rn(gx, __fmul_rn(2.f, a12));
  gx = __fadd_rn(gx, __fmul_rn(-1.f, a20));
  gx = __fadd_rn(gx, a22);
  gy = a00;
  gy = __fadd_rn(gy, __fmul_rn(2.f, a01));
  gy = __fadd_rn(gy, a02);
  gy = __fadd_rn(gy, __fmul_rn(-1.f, a20));
  gy = __fadd_rn(gy, __fmul_rn(-2.f, a21));
  gy = __fadd_rn(gy, __fmul_rn(-1.f, a22));
}

__device__ __forceinline__ bool sobel_gxgy(const float* __restrict__ x, int pix,
                                           float& gx, float& gy) {
  int r = pix >> 10, c = pix & (W - 1);
  if (r < 1 || r > H - 2 || c < 1 || c > W - 2) return false;
  sobel_core(x[(r - 1) * W + c - 1], x[(r - 1) * W + c], x[(r - 1) * W + c + 1],
             x[r * W + c - 1], x[r * W + c + 1],
             x[(r + 1) * W + c - 1], x[(r + 1) * W + c], x[(r + 1) * W + c + 1], gx, gy);
  return true;
}
__device__ __forceinline__ float sobel_edge(const float* __restrict__ x, int pix) {
  float gx, gy;
  if (!sobel_gxgy(x, pix, gx, gy)) return 0.f;
  return sqrtf(__fadd_rn(__fmul_rn(gx, gx), __fmul_rn(gy, gy)));
}

// 4 consecutive pixels (same row, c0 multiple of 4). Fills e[0..3].
__device__ __forceinline__ void sobel_edge4(const float* __restrict__ x, int r, int c0,
                                            float e[4]) {
  if (r >= 1 && r <= H - 2 && c0 >= 4 && c0 <= W - 8) {
    float up[6], md[6], dn[6];
#pragma unroll
    for (int k = 0; k < 6; k++) {
      up[k] = __ldg(&x[(r - 1) * W + c0 - 1 + k]);
      md[k] = __ldg(&x[r * W + c0 - 1 + k]);
      dn[k] = __ldg(&x[(r + 1) * W + c0 - 1 + k]);
    }
#pragma unroll
    for (int k = 0; k < 4; k++) {
      float gx, gy;
      sobel_core(up[k], up[k + 1], up[k + 2], md[k], md[k + 2],
                 dn[k], dn[k + 1], dn[k + 2], gx, gy);
      e[k] = sqrtf(__fadd_rn(__fmul_rn(gx, gx), __fmul_rn(gy, gy)));
    }
  } else {
#pragma unroll
    for (int k = 0; k < 4; k++) e[k] = sobel_edge(x, r * W + c0 + k);
  }
}

// ---------------- kernels ----------------------------------------------------
__global__ void k_init() {
  int i = threadIdx.x;
  if (i < NIMG) {
    g_edgemax[i] = 0u; g_maskcnt[i] = 0; g_maxdiff[i] = 0u; g_validcnt[i] = 0;
    g_sum_eq[i] = 0.0; g_sum_ne[i] = 0.0;
  }
}

__global__ void k_edgemax(const float* __restrict__ images) {
  int img = blockIdx.y;
  int t = blockIdx.x * blockDim.x + threadIdx.x;     // 0..HW/4-1
  int pix0 = t * 4;
  int r = pix0 >> 10, c0 = pix0 & (W - 1);
  const float* x = images + (size_t)img * 3 * HW;    // channel 0
  float e[4];
  sobel_edge4(x, r, c0, e);
  float m = fmaxf(fmaxf(e[0], e[1]), fmaxf(e[2], e[3]));
  unsigned um = __reduce_max_sync(0xFFFFFFFFu, __float_as_uint(m));  // e >= 0
  __shared__ unsigned sm[8];
  if ((threadIdx.x & 31) == 0) sm[threadIdx.x >> 5] = um;
  __syncthreads();
  if (threadIdx.x == 0) {
    unsigned mx = sm[0];
#pragma unroll
    for (int w = 1; w < 8; w++) mx = max(mx, sm[w]);
    atomicMax(&g_edgemax[img], mx);
  }
}

__global__ void k_mask(const float* __restrict__ images, const float* __restrict__ tgt,
                       const float* __restrict__ depth) {
  int img = blockIdx.y;
  int t = blockIdx.x * blockDim.x + threadIdx.x;     // 0..HW/4-1
  int pix0 = t * 4;
  int r = pix0 >> 10, c0 = pix0 & (W - 1);
  float thresh = __fmul_rn(0.1f, __uint_as_float(g_edgemax[img]));
  const float* x = images + (size_t)img * 3 * HW;
  float e[4];
  sobel_edge4(x, r, c0, e);
  float4 d4 = __ldg((const float4*)(depth + (size_t)img * HW + pix0));
  float4 t4 = __ldg((const float4*)(tgt + (size_t)img * HW + pix0));
  float dd[4] = {d4.x, d4.y, d4.z, d4.w};
  float tg[4] = {t4.x, t4.y, t4.z, t4.w};
  uint32_t nib = 0;
#pragma unroll
  for (int k = 0; k < 4; k++) {
    bool m = (e[k] >= thresh) && (dd[k] > -0.001f) && (dd[k] < 80.0f) && !(tg[k] == 80.0f);
    if (m) nib |= (1u << k);
  }
  int lane = threadIdx.x & 31;
  uint32_t wordv = 0;
#pragma unroll
  for (int k = 0; k < 8; k++) {
    uint32_t nb = __shfl_sync(0xFFFFFFFFu, nib, (lane & 3) * 8 + k);
    wordv |= nb << (4 * k);
  }
  if (lane < 4) {
    int gwarp = (blockIdx.x * blockDim.x + threadIdx.x) >> 5;  // 128 px per warp
    g_maskbits[img * NWORDS + gwarp * 4 + lane] = wordv;
  }
  int cnt = __reduce_add_sync(0xFFFFFFFFu, __popc(nib));
  __shared__ int cnts[8];
  if (lane == 0) cnts[threadIdx.x >> 5] = cnt;
  __syncthreads();
  if (threadIdx.x == 0) {
    int s = 0;
#pragma unroll
    for (int w = 0; w < 8; w++) s += cnts[w];
    atomicAdd(&g_maskcnt[img], s);
  }
}

// Fused pyramid levels 1..13: one thread = one mask word (32 leaves, levels 1..5
// in registers), shared pairwise reduction for levels 6..13 (8192 leaves/block).
// Same __fadd_rn pairing as the reference associative_scan at every level.
__global__ void k_pyr() {
  int img = blockIdx.y;
  int cb = blockIdx.x;                                // chunk 0..127
  int t = threadIdx.x;                                // 0..255
  int wi = cb * 256 + t;                              // word index
  float* gp = g_pyr + (size_t)img * PYR_SZ;
  float S = (float)g_maskcnt[img];
  float v = __fdiv_rn(1.0f, fmaxf(S, 1.0f));
  uint32_t wrd = g_maskbits[img * NWORDS + wi];

  float l1[16];
#pragma unroll
  for (int k = 0; k < 16; k++) {
    float a = ((wrd >> (2 * k)) & 1u) ? v : 0.f;
    float b = ((wrd >> (2 * k + 1)) & 1u) ? v : 0.f;
    l1[k] = __fadd_rn(a, b);
  }
  float l2[8], l3[4], l4[2], l5;
#pragma unroll
  for (int k = 0; k < 8; k++) l2[k] = __fadd_rn(l1[2 * k], l1[2 * k + 1]);
#pragma unroll
  for (int k = 0; k < 4; k++) l3[k] = __fadd_rn(l2[2 * k], l2[2 * k + 1]);
#pragma unroll
  for (int k = 0; k < 2; k++) l4[k] = __fadd_rn(l3[2 * k], l3[2 * k + 1]);
  l5 = __fadd_rn(l4[0], l4[1]);

  float4* p1 = (float4*)(gp + lvlOff(1) + wi * 16);
#pragma unroll
  for (int k = 0; k < 4; k++)
    p1[k] = make_float4(l1[4 * k], l1[4 * k + 1], l1[4 * k + 2], l1[4 * k + 3]);
  float4* p2 = (float4*)(gp + lvlOff(2) + wi * 8);
  p2[0] = make_float4(l2[0], l2[1], l2[2], l2[3]);
  p2[1] = make_float4(l2[4], l2[5], l2[6], l2[7]);
  ((float4*)(gp + lvlOff(3) + wi * 4))[0] = make_float4(l3[0], l3[1], l3[2], l3[3]);
  ((float2*)(gp + lvlOff(4) + wi * 2))[0] = make_float2(l4[0], l4[1]);
  gp[lvlOff(5) + wi] = l5;

  __shared__ float sm[256];
  sm[t] = l5;
  __syncthreads();
#pragma unroll
  for (int b = 6; b <= 13; b++) {
    int n = 8192 >> b;                                // outputs this level per block
    float x = 0.f;
    if (t < n) {
      x = __fadd_rn(sm[2 * t], sm[2 * t + 1]);
      gp[lvlOff(b) + cb * n + t] = x;
    }
    __syncthreads();
    if (t < n) sm[t] = x;
    __syncthreads();
  }
}

// Levels 14..20 (from level 13: 128 elems/img). One block per image.
__global__ void k_pyr_tail() {
  int img = blockIdx.x;
  float* base = g_pyr + (size_t)img * PYR_SZ;
  for (int b = 14; b <= 20; b++) {
    int n = 1 << (20 - b);
    int srcOff = lvlOff(b - 1), dstOff = lvlOff(b);
    for (int i = threadIdx.x; i < n; i += blockDim.x)
      base[dstOff + i] = __fadd_rn(base[srcOff + 2 * i], base[srcOff + 2 * i + 1]);
    __syncthreads();
  }
}

__device__ __forceinline__ float leaf_at(const uint32_t* __restrict__ mb, int i, float v) {
  uint32_t wrd = __ldg(&mb[i >> 5]);
  return ((wrd >> (i & 31)) & 1u) ? v : 0.f;
}

// Generic cumsum[m-1] via aligned-block decomposition (reference association).
__device__ __forceinline__ float cumsum_generic(const float* __restrict__ pyr,
                                                const uint32_t* __restrict__ mb,
                                                float v, uint32_t m) {
  float acc = 0.f;
  uint32_t off = 0;
#pragma unroll
  for (int b = 20; b >= 1; b--) {
    if ((m >> b) & 1u) {
      acc = __fadd_rn(acc, __ldg(&pyr[lvlOff(b) + (off >> b)]));
      off += (1u << b);
    }
  }
  if (m & 1u) acc = __fadd_rn(acc, leaf_at(mb, (int)off, v));
  return acc;
}

__global__ void k_sample(LaunchParams P, const float* __restrict__ inp,
                         const float* __restrict__ tgt,
                         const float* __restrict__ images) {
  int j = blockIdx.x * blockDim.x + threadIdx.x;
  int img = blockIdx.y;
  if (j >= NP) return;
  const float* pyr = g_pyr + (size_t)img * PYR_SZ;
  const uint32_t* mb = g_maskbits + img * NWORDS;
  float S = (float)g_maskcnt[img];
  float v = __fdiv_rn(1.0f, fmaxf(S, 1.0f));

  uint32_t ub = pbits32(P.k1[img], (uint32_t)j);
  float u = __uint_as_float((ub >> 9) | 0x3F800000u) - 1.0f;
  float T = __ldg(&pyr[lvlOff(20)]);
  float r = __fmul_rn(T, __fsub_rn(1.0f, u));

  // searchsorted 'scan': incremental tree descent (iterations at b=19..1),
  // then two generic evaluations (m = low+2, low+1) exactly as the reference.
  int low = 0;
  float A = 0.f;
#pragma unroll 1
  for (int b = 19; b >= 1; b--) {
    int mid = low + (1 << b);
    float t1 = __fadd_rn(A, __ldg(&pyr[lvlOff(b) + (low >> b)]));
    float acc = __fadd_rn(t1, leaf_at(mb, mid, v));
    if (!(r <= acc)) { A = t1; low = mid; }
  }
  {
    float acc = cumsum_generic(pyr, mb, v, (uint32_t)low + 2u);
    if (!(r <= acc)) low = low + 1;
  }
  int idx;
  {
    float acc = cumsum_generic(pyr, mb, v, (uint32_t)low + 1u);
    idx = (r <= acc) ? low : low + 1;
  }
  if (idx > HW - 1) idx = HW - 1;

  int sh = idx >> 10, sw = idx & (W - 1);
  float th = 0.f;
  {
    float gx, gy;
    const float* x = images + (size_t)img * 3 * HW;
    if (sobel_gxgy(x, idx, gx, gy)) th = atan2f(gy, gx);
  }
  float c0 = cosf(th), s0 = sinf(th);
  float xx = __fadd_rn(__fadd_rn(th, 1.5707964f), 3.1415927f);
  float tm = fmodf(xx, 6.2831855f);
  if (tm != 0.0f && tm < 0.0f) tm = __fadd_rn(tm, 6.2831855f);
  float th2 = __fsub_rn(tm, 3.1415927f);
  float s2 = sinf(th2), c2 = cosf(th2);
  bool pd = P.pdir[img] != 0;

  int rows[4], cols[4];
  bool ok = true;
#pragma unroll
  for (int i = 0; i < 4; i++) {
    uint32_t f = (uint32_t)(i * NP + j);
    uint32_t hb = pbits32(P.k2a[img], f);
    uint32_t lb = pbits32(P.k2b[img], f);
    uint32_t offr = ((hb % 29u) * 16u + (lb % 29u)) % 29u;
    float d = (float)(2u + offr);
    if (i < 2) d = -d;
    int col, row;
    if (pd) {
      col = sw + (int)rintf(__fmul_rn(d, c0));
      row = sh + (int)rintf(__fmul_rn(d, s0));
    } else {
      col = sw + (int)rintf(__fmul_rn(d, s2));
      row = sh + (int)rintf(__fmul_rn(d, c2));
    }
    ok = ok && (col >= 0) && (col <= W - 1) && (row >= 0) && (row <= H - 1);
    cols[i] = min(max(col, 0), W - 1);
    rows[i] = min(max(row, 0), H - 1);
  }
  const float* ip = inp + (size_t)img * HW;
  const float* tp = tgt + (size_t)img * HW;
  float tv[4];
#pragma unroll
  for (int i = 0; i < 4; i++) {
    int p = rows[i] * W + cols[i];
    float ivv = __ldg(&ip[p]);
    tv[i] = __ldg(&tp[p]);
    g_ivals[img][j][i] = ivv;
    g_tvals[img][j][i] = tv[i];
  }
  g_validf[img][j] = ok ? 1 : 0;
  if (ok) {
    float m0 = fabsf(__fsub_rn(tv[0], tv[1]));
    float m1 = fabsf(__fsub_rn(tv[1], tv[2]));
    float m2 = fabsf(__fsub_rn(tv[2], tv[3]));
    float mm = fmaxf(m0, fmaxf(m1, m2));
    atomicMax(&g_maxdiff[img], __float_as_uint(mm));
    atomicAdd(&g_validcnt[img], 1);
  }
}

__global__ void k_loss() {
  int j = blockIdx.x * blockDim.x + threadIdx.x;
  int img = blockIdx.y;
  double se = 0.0, sn = 0.0;
  if (j < NP) {
    float md = __uint_as_float(g_maxdiff[img]);
    float denom = __fadd_rn(md, 1e-6f);
    float vm = g_validf[img][j] ? 1.0f : 0.0f;
    const float CHI = (float)(1.0 + 0.03);
    const float CLO = (float)(1.0 / (1.0 + 0.03));
#pragma unroll
    for (int k = 0; k < 3; k++) {
      float tA = g_tvals[img][j][k], tB = g_tvals[img][j][k + 1];
      float iA = g_ivals[img][j][k], iB = g_ivals[img][j][k + 1];
      float ratio = __fdiv_rn(__fadd_rn(tA, 1e-6f), __fadd_rn(tB, 1e-6f));
      float ad = fabsf(__fsub_rn(tA, tB));
      float tw = expf(__fdiv_rn(ad, denom));
      bool eqb = (ratio < CHI) && (ratio > CLO);
      float eqf = eqb ? 1.0f : 0.0f;
      float label = (ratio >= CHI) ? 1.0f : ((ratio <= CLO) ? -1.0f : 0.0f);
      float dd = __fsub_rn(iA, iB);
      float el = __fmul_rn(__fdiv_rn(__fmul_rn(dd, dd), tw), eqf);
      float z = __fmul_rn(__fsub_rn(iB, iA), label);
      float ue = __fmul_rn(log1pf(expf(z)), __fsub_rn(1.0f, eqf));
      se += (double)__fmul_rn(el, vm);
      sn += (double)__fmul_rn(ue, vm);
    }
  }
  __shared__ double sh_se[128];
  __shared__ double sh_sn[128];
  sh_se[threadIdx.x] = se; sh_sn[threadIdx.x] = sn;
  __syncthreads();
  for (int s = blockDim.x / 2; s > 0; s >>= 1) {
    if ((int)threadIdx.x < s) {
      sh_se[threadIdx.x] += sh_se[threadIdx.x + s];
      sh_sn[threadIdx.x] += sh_sn[threadIdx.x + s];
    }
    __syncthreads();
  }
  if (threadIdx.x == 0) {
    atomicAdd(&g_sum_eq[img], sh_se[0]);
    atomicAdd(&g_sum_ne[img], sh_sn[0]);
  }
}

__global__ void k_final(float* out, int out_size) {
  if (threadIdx.x == 0 && blockIdx.x == 0) {
    float ls = 0.f, cs = 0.f;
    for (int i = 0; i < NIMG; i++) {
      float nv = 3.0f * (float)g_validcnt[i];
      float cnt = fmaxf(nv, 1.0f);
      float li = (float)(g_sum_eq[i] / (double)cnt + g_sum_ne[i] / (double)cnt);
      ls += li; cs += nv;
    }
    if (out_size >= 1) out[0] = ls / 8.0f;
    if (out_size >= 2) out[1] = cs / 8.0f;
  }
}

// ---------------- host --------------------------------------------------------
extern "C" void kernel_launch(void* const* d_in, const int* in_sizes, int n_in,
                              void* d_out, int out_size) {
  const float* inputs  = (const float*)d_in[0];
  const float* targets = (const float*)d_in[1];
  const float* images  = (const float*)d_in[2];
  const float* depth   = (const float*)d_in[3];
  float* out = (float*)d_out;
  (void)in_sizes; (void)n_in;

  LaunchParams P;
  uint32_t root[2] = {0u, 42u};   // jax.random.key(42)
  for (int i = 0; i < NIMG; i++) {
    uint32_t ik[2];
    tf_block(root, (uint32_t)i, ik[0], ik[1]);         // keys = split(key(42), 8)
    uint32_t k1[2], k2[2], k3[2];
    tf_block(ik, 0u, k1[0], k1[1]);                    // k1,k2,k3 = split(key, 3)
    tf_block(ik, 1u, k2[0], k2[1]);
    tf_block(ik, 2u, k3[0], k3[1]);
    P.k1[i][0] = k1[0]; P.k1[i][1] = k1[1];
    tf_block(k2, 0u, P.k2a[i][0], P.k2a[i][1]);        // randint: ka, kb = split(k2)
    tf_block(k2, 1u, P.k2b[i][0], P.k2b[i][1]);
    uint32_t bits = pbits32(k3, 0u);                   // uniform(k3) scalar
    uint32_t fb = (bits >> 9) | 0x3F800000u;
    float uu; memcpy(&uu, &fb, 4); uu -= 1.0f;
    P.pdir[i] = (uu < 0.5f) ? 1u : 0u;
  }

  k_init<<<1, 32>>>();
  dim3 gs4(HW / 4 / 256, NIMG);
  k_edgemax<<<gs4, 256>>>(images);
  k_mask<<<gs4, 256>>>(images, targets, depth);
  k_pyr<<<dim3(128, NIMG), 256>>>();
  k_pyr_tail<<<NIMG, 64>>>();
  dim3 gsamp((NP + 127) / 128, NIMG);
  k_sample<<<gsamp, 128>>>(P, inputs, targets, images);
  k_loss<<<gsamp, 128>>>();
  k_final<<<1, 1>>>(out, out_size);
}